// round 16
// baseline (speedup 1.0000x reference)
#include <cuda_runtime.h>
#include <cuda_fp16.h>
#include <cstdint>
#include <math.h>

#define NIMG 256
#define NREG 36
#define NCAP 256
#define MAXW 60
#define CAPW 64
#define DIM  1024

#define SMOOTH 9.0f
#define EPSV   1e-8f
#define LEAK   0.1f

// ---------------------------------------------------------------------------
// Device global scratch
// ---------------------------------------------------------------------------
__device__ __half g_caps_h[NCAP * CAPW * DIM];
__device__ __half g_imgs_h[NIMG * NREG * DIM];
__device__ float g_G[NIMG * NREG * NREG];
__device__ float g_w1[NCAP * MAXW];

// ---------------------------------------------------------------------------
// Helpers
// ---------------------------------------------------------------------------
__device__ __forceinline__ uint32_t smem_to_u32(const void* p) {
    uint32_t a;
    asm("{ .reg .u64 t; cvta.to.shared.u64 t, %1; cvt.u32.u64 %0, t; }"
        : "=r"(a) : "l"(p));
    return a;
}
__device__ __forceinline__ void cp16(uint32_t dst, const void* src) {
    asm volatile("cp.async.cg.shared.global [%0], [%1], 16;" :: "r"(dst), "l"(src) : "memory");
}
__device__ __forceinline__ void ldsm_x4(uint32_t &r0, uint32_t &r1, uint32_t &r2,
                                        uint32_t &r3, uint32_t addr) {
    asm volatile("ldmatrix.sync.aligned.m8n8.x4.shared.b16 {%0,%1,%2,%3}, [%4];"
                 : "=r"(r0), "=r"(r1), "=r"(r2), "=r"(r3) : "r"(addr));
}
__device__ __forceinline__ void mma_f16(float &c0, float &c1, float &c2, float &c3,
                                        uint32_t a0, uint32_t a1, uint32_t a2, uint32_t a3,
                                        uint32_t b0, uint32_t b1) {
    asm volatile("mma.sync.aligned.m16n8k16.row.col.f32.f16.f16.f32 "
                 "{%0,%1,%2,%3}, {%4,%5,%6,%7}, {%8,%9}, {%0,%1,%2,%3};"
                 : "+f"(c0), "+f"(c1), "+f"(c2), "+f"(c3)
                 : "r"(a0), "r"(a1), "r"(a2), "r"(a3), "r"(b0), "r"(b1));
}
__device__ __forceinline__ unsigned long long pack2(float lo, float hi) {
    unsigned long long r;
    asm("mov.b64 %0, {%1, %2};" : "=l"(r) : "f"(lo), "f"(hi));
    return r;
}
__device__ __forceinline__ void unpack2(unsigned long long v, float &lo, float &hi) {
    asm("mov.b64 {%0, %1}, %2;" : "=f"(lo), "=f"(hi) : "l"(v));
}
__device__ __forceinline__ void ffma2(unsigned long long &d,
                                      unsigned long long a,
                                      unsigned long long b) {
    asm("fma.rn.f32x2 %0, %1, %2, %0;" : "+l"(d) : "l"(a), "l"(b));
}
__device__ __forceinline__ float warpSum(float v) {
    v += __shfl_xor_sync(0xffffffffu, v, 16);
    v += __shfl_xor_sync(0xffffffffu, v, 8);
    v += __shfl_xor_sync(0xffffffffu, v, 4);
    v += __shfl_xor_sync(0xffffffffu, v, 2);
    v += __shfl_xor_sync(0xffffffffu, v, 1);
    return v;
}
__device__ __forceinline__ float dot4(float4 a, float4 b) {
    return a.x * b.x + a.y * b.y + a.z * b.z + a.w * b.w;
}

// ---------------------------------------------------------------------------
// Merged prep: blocks [0,256) caps; [256,512) imgs + Gram (4x4 reg-blocked)
// ---------------------------------------------------------------------------
__global__ void prep_kernel(const float* __restrict__ imgs,
                            const float* __restrict__ caps,
                            const int* __restrict__ cap_lens) {
    __shared__ float chunk[NREG * 132];
    if (blockIdx.x < 256) {
        const int c = blockIdx.x;
        const int wid = threadIdx.x >> 5, lane = threadIdx.x & 31;
        const int len = cap_lens[c];
        for (int w = wid; w < CAPW; w += 8) {
            size_t dsto = ((size_t)c * CAPW + w) * DIM;
            if (w < len) {
                const float* row = caps + ((size_t)c * MAXW + w) * DIM;
                float ss = 0.f;
#pragma unroll
                for (int j = 0; j < 8; j++) {
                    float4 v = *(const float4*)(row + j * 128 + lane * 4);
                    ss += v.x * v.x + v.y * v.y + v.z * v.z + v.w * v.w;
                    size_t o = dsto + j * 128 + lane * 4;
                    *(__half2*)(g_caps_h + o)     = __floats2half2_rn(v.x, v.y);
                    *(__half2*)(g_caps_h + o + 2) = __floats2half2_rn(v.z, v.w);
                }
                ss = warpSum(ss);
                if (lane == 0 && w < MAXW) g_w1[c * MAXW + w] = sqrtf(ss);
            } else {
                uint2 z = make_uint2(0u, 0u);
#pragma unroll
                for (int j = 0; j < 8; j++)
                    *(uint2*)(g_caps_h + dsto + j * 128 + lane * 4) = z;
                if (lane == 0 && w < MAXW) g_w1[c * MAXW + w] = 0.f;
            }
        }
    } else {
        const int i = blockIdx.x - 256;
        const int ty = threadIdx.x / 9;
        const int tx = threadIdx.x % 9;
        float acc[4][4];
#pragma unroll
        for (int u = 0; u < 4; u++)
#pragma unroll
            for (int v = 0; v < 4; v++) acc[u][v] = 0.f;

        for (int d0 = 0; d0 < DIM; d0 += 128) {
            __syncthreads();
            for (int idx = threadIdx.x; idx < NREG * 32; idx += 256) {
                int r = idx >> 5, dq = idx & 31;
                size_t e = ((size_t)i * NREG + r) * DIM + d0 + dq * 4;
                float4 v = *(const float4*)(imgs + e);
                *(float4*)(chunk + r * 132 + dq * 4) = v;
                *(__half2*)(g_imgs_h + e)     = __floats2half2_rn(v.x, v.y);
                *(__half2*)(g_imgs_h + e + 2) = __floats2half2_rn(v.z, v.w);
            }
            __syncthreads();
            if (threadIdx.x < 81) {
                const float4* A0 = (const float4*)(chunk + (ty * 4 + 0) * 132);
                const float4* A1 = (const float4*)(chunk + (ty * 4 + 1) * 132);
                const float4* A2 = (const float4*)(chunk + (ty * 4 + 2) * 132);
                const float4* A3 = (const float4*)(chunk + (ty * 4 + 3) * 132);
                const float4* B0 = (const float4*)(chunk + (tx * 4 + 0) * 132);
                const float4* B1 = (const float4*)(chunk + (tx * 4 + 1) * 132);
                const float4* B2 = (const float4*)(chunk + (tx * 4 + 2) * 132);
                const float4* B3 = (const float4*)(chunk + (tx * 4 + 3) * 132);
#pragma unroll 8
                for (int q = 0; q < 32; q++) {
                    float4 a0 = A0[q], a1 = A1[q], a2 = A2[q], a3 = A3[q];
                    float4 b0 = B0[q], b1 = B1[q], b2 = B2[q], b3 = B3[q];
                    acc[0][0] += dot4(a0, b0); acc[0][1] += dot4(a0, b1);
                    acc[0][2] += dot4(a0, b2); acc[0][3] += dot4(a0, b3);
                    acc[1][0] += dot4(a1, b0); acc[1][1] += dot4(a1, b1);
                    acc[1][2] += dot4(a1, b2); acc[1][3] += dot4(a1, b3);
                    acc[2][0] += dot4(a2, b0); acc[2][1] += dot4(a2, b1);
                    acc[2][2] += dot4(a2, b2); acc[2][3] += dot4(a2, b3);
                    acc[3][0] += dot4(a3, b0); acc[3][1] += dot4(a3, b1);
                    acc[3][2] += dot4(a3, b2); acc[3][3] += dot4(a3, b3);
                }
            }
        }
        if (threadIdx.x < 81) {
            float* Gi = g_G + (size_t)i * NREG * NREG;
#pragma unroll
            for (int u = 0; u < 4; u++) {
                float4 v0 = make_float4(acc[u][0], acc[u][1], acc[u][2], acc[u][3]);
                *(float4*)(Gi + (ty * 4 + u) * NREG + tx * 4) = v0;
            }
        }
    }
}

// ---------------------------------------------------------------------------
// Main fused kernel: fp16 GEMM M=128 x N=144 x K=1024 + SCAN epilogue.
// 384 threads / 12 warps (warp tile 32x48, 3 clean n-cols of 48),
// 3-stage pipeline, 2 CTAs/SM -> 24 warps/SM.
// ---------------------------------------------------------------------------
#define STAGE_BYTES 34816
#define SB_OFF      16384
#define SOFF_SCALE  75776
#define SOFF_W1     76928
#define SOFF_WP     77440
#define SOFF_G      77504
#define SMEM_TOTAL_MAIN 104448
#define NCHUNK 16
#define SSTRIDE 148   // floats per S row

__device__ __forceinline__ void load_stage(uint32_t sbase, int chunk, int tid,
                                           int arowbase, int browbase) {
    const int k0 = chunk << 6;
    const uint32_t sA = sbase + (chunk % 3) * STAGE_BYTES;
    const uint32_t sB = sA + SB_OFF;
#pragma unroll
    for (int t = 0; t < 3; t++) {              // 1024 A lines
        int o = tid + t * 384;
        if (o < 1024) {
            int row = o >> 3, seg = o & 7;
            cp16(sA + row * 128 + (((seg ^ (row & 7))) << 4),
                 g_caps_h + (((size_t)(arowbase + row)) << 10) + k0 + (seg << 3));
        }
    }
#pragma unroll
    for (int t = 0; t < 3; t++) {              // 1152 B lines (exact)
        int o = tid + t * 384;
        int row = o >> 3, seg = o & 7;
        cp16(sB + row * 128 + (((seg ^ (row & 7))) << 4),
             g_imgs_h + (((size_t)(browbase + row)) << 10) + k0 + (seg << 3));
    }
    asm volatile("cp.async.commit_group;" ::: "memory");
}

__global__ void __launch_bounds__(384, 2)
main_kernel(const int* __restrict__ cap_lens, float* __restrict__ out) {
    extern __shared__ __align__(16) char smem[];
    const uint32_t sb = smem_to_u32(smem);
    const int tid = threadIdx.x, lane = tid & 31, wid = tid >> 5;
    const int c0 = blockIdx.y * 2;
    const int i0 = blockIdx.x * 4;
    const int arowbase = blockIdx.y * 128;
    const int browbase = blockIdx.x * 144;

    float acc[48];
#pragma unroll
    for (int j = 0; j < 48; j++) acc[j] = 0.f;

    load_stage(sb, 0, tid, arowbase, browbase);
    load_stage(sb, 1, tid, arowbase, browbase);

    const int mstrip = wid & 3;               // 4 m-strips of 32 rows
    const int mbase = mstrip * 32;
    const int ncb = (wid >> 2) * 48;          // 3 n-cols of 48
    const bool gemm_active =
        ((mstrip & 1) == 0) || (cap_lens[c0 + (mstrip >> 1)] > 32);

    const int a_roff = lane & 15;
    const int a_seg0 = lane >> 4;
    const int b_roff = ((lane >> 4) << 3) + (lane & 7);
    const int b_seg0 = (lane >> 3) & 1;
    const int sw = lane & 7;

    for (int i = 0; i < NCHUNK; i++) {
        if (i == NCHUNK - 1) asm volatile("cp.async.wait_group 0;" ::: "memory");
        else                 asm volatile("cp.async.wait_group 1;" ::: "memory");
        __syncthreads();
        if (i + 2 < NCHUNK)
            load_stage(sb, i + 2, tid, arowbase, browbase);

        if (gemm_active) {
            const uint32_t As = sb + (i % 3) * STAGE_BYTES;
            const uint32_t Bs = As + SB_OFF;
#pragma unroll
            for (int ks = 0; ks < 4; ks++) {
                uint32_t a[2][4];
#pragma unroll
                for (int s2 = 0; s2 < 2; s2++) {
                    int row = mbase + s2 * 16 + a_roff;
                    int seg = (ks * 2 + a_seg0) ^ sw;
                    ldsm_x4(a[s2][0], a[s2][1], a[s2][2], a[s2][3],
                            As + row * 128 + (seg << 4));
                }
#pragma unroll
                for (int t = 0; t < 3; t++) {
                    uint32_t b0, b1, b2, b3;
                    int row = ncb + t * 16 + b_roff;
                    int seg = (ks * 2 + b_seg0) ^ sw;
                    ldsm_x4(b0, b1, b2, b3, Bs + row * 128 + (seg << 4));
#pragma unroll
                    for (int s2 = 0; s2 < 2; s2++) {
                        int j0 = s2 * 24 + t * 8;
                        mma_f16(acc[j0 + 0], acc[j0 + 1], acc[j0 + 2], acc[j0 + 3],
                                a[s2][0], a[s2][1], a[s2][2], a[s2][3], b0, b1);
                        mma_f16(acc[j0 + 4], acc[j0 + 5], acc[j0 + 6], acc[j0 + 7],
                                a[s2][0], a[s2][1], a[s2][2], a[s2][3], b2, b3);
                    }
                }
            }
        }
    }
    __syncthreads();   // stages fully consumed before S/Gram overwrite them

    // ---------------- write S (skip dead strips) + stage Gram / w1 ---------
    float* S = (float*)smem;
    if (gemm_active) {
        const int cA = (lane & 3) * 2;
        const int rA = lane >> 2;
#pragma unroll
        for (int s2 = 0; s2 < 2; s2++) {
            int r1 = mbase + s2 * 16 + rA;
#pragma unroll
            for (int j = 0; j < 6; j++) {
                int col = ncb + j * 8 + cA;
                *(float2*)(S + r1 * SSTRIDE + col) =
                    make_float2(acc[s2 * 24 + j * 4 + 0], acc[s2 * 24 + j * 4 + 1]);
                *(float2*)(S + (r1 + 8) * SSTRIDE + col) =
                    make_float2(acc[s2 * 24 + j * 4 + 2], acc[s2 * 24 + j * 4 + 3]);
            }
        }
    }
    {
        float* Gs = (float*)(smem + SOFF_G);
        if (tid < 4 * NREG) {
            int blk = tid / NREG, r = tid - blk * NREG;
            const float4* src = (const float4*)(g_G + ((size_t)(i0 + blk) * NREG + r) * NREG);
            float4* dst = (float4*)(Gs + (blk * NREG + r) * 40);
#pragma unroll
            for (int q = 0; q < 9; q++) dst[q] = src[q];
            dst[9] = make_float4(0.f, 0.f, 0.f, 0.f);
        }
        float* w1s = (float*)(smem + SOFF_W1);
        if (tid >= 256) {
            int p = tid - 256;
            int cc = p >> 6, w = p & 63;
            w1s[p] = (w < MAXW) ? g_w1[(c0 + cc) * MAXW + w] : 0.f;
        }
    }
    __syncthreads();

    // ---------------- column norms -> scale (float4, len-bounded) ----------
    float* scaleF = (float*)(smem + SOFF_SCALE);
    if (tid < 72) {
        int cap = tid >= 36;
        int j4 = (tid - cap * 36) * 4;
        int lenc = cap_lens[c0 + cap];
        const float* p = S + (cap * 64) * SSTRIDE + j4;
        float4 ssum = make_float4(0.f, 0.f, 0.f, 0.f);
        for (int w = 0; w < lenc; w++) {
            float4 v = *(const float4*)(p + w * SSTRIDE);
            v.x = (v.x < 0.f) ? LEAK * v.x : v.x;
            v.y = (v.y < 0.f) ? LEAK * v.y : v.y;
            v.z = (v.z < 0.f) ? LEAK * v.z : v.z;
            v.w = (v.w < 0.f) ? LEAK * v.w : v.w;
            ssum.x += v.x * v.x; ssum.y += v.y * v.y;
            ssum.z += v.z * v.z; ssum.w += v.w * v.w;
        }
        float4 sc;
        sc.x = SMOOTH / (sqrtf(ssum.x) + EPSV);
        sc.y = SMOOTH / (sqrtf(ssum.y) + EPSV);
        sc.z = SMOOTH / (sqrtf(ssum.z) + EPSV);
        sc.w = SMOOTH / (sqrtf(ssum.w) + EPSV);
        *(float4*)(scaleF + cap * 144 + j4) = sc;
    }
    __syncthreads();

    // ---------------- epilogue: 512 tasks (row, blk) over 384 threads ------
    {
        float* wp = (float*)(smem + SOFF_WP);
        for (int T = tid; T < 512; T += 384) {
            const int row = T & 127;
            const int blk = T >> 7;
            const int wt  = T >> 5;           // warp-task id 0..15
            const int cap = row >> 6;
            const int word = row & 63;
            const int mylen = cap_lens[c0 + cap];
            const bool warp_act = ((row & 32) == 0) || (mylen > 32);

            if (!warp_act) {
                if (lane == 0) wp[wt] = 0.f;
                continue;
            }
            const bool valid = word < mylen;
            const float myw1 = ((const float*)(smem + SOFF_W1))[row];
            const float* Srow = S + row * SSTRIDE;
            const float* scl = scaleF + cap * 144 + blk * 36;

            float raw[36], e[40];
            {
                const float4* p4 = (const float4*)(Srow + blk * 36);
#pragma unroll
                for (int q = 0; q < 9; q++) {
                    float4 v = p4[q];
                    raw[q * 4 + 0] = v.x; raw[q * 4 + 1] = v.y;
                    raw[q * 4 + 2] = v.z; raw[q * 4 + 3] = v.w;
                }
            }
            float se = 0.f;
#pragma unroll
            for (int r = 0; r < 36; r++) {
                float v = raw[r];
                float l = ((v < 0.f) ? LEAK * v : v) * scl[r];
                e[r] = __expf(l);
                se += e[r];
            }
            e[36] = 0.f; e[37] = 0.f; e[38] = 0.f; e[39] = 0.f;
            float inv = 1.f / se;
            float w12 = 0.f;
#pragma unroll
            for (int r = 0; r < 36; r++) w12 += e[r] * raw[r];
            w12 *= inv;

            unsigned long long ep[20];
#pragma unroll
            for (int q = 0; q < 20; q++) ep[q] = pack2(e[2 * q], e[2 * q + 1]);
            const float* Gbase =
                (const float*)(smem + SOFF_G) + (size_t)blk * NREG * 40;
            float t = 0.f;
#pragma unroll
            for (int r = 0; r < 36; r++) {
                const float* grow = Gbase + r * 40;
                const unsigned long long* grow2 = (const unsigned long long*)grow;
                float head = 0.f;
                int q0 = r + 1;
                if (q0 & 1) { head = grow[q0] * e[q0]; q0++; }
                unsigned long long d2 = 0ull;
#pragma unroll
                for (int qq = q0 >> 1; qq < 20; qq++) ffma2(d2, grow2[qq], ep[qq]);
                float dlo, dhi;
                unpack2(d2, dlo, dhi);
                t += e[r] * (grow[r] * e[r] + 2.f * (head + dlo + dhi));
            }
            float w2 = sqrtf(t) * inv;
            float sim = w12 / fmaxf(myw1 * w2, EPSV);
            sim = valid ? sim : 0.f;

            float ssum = warpSum(sim);
            if (lane == 0) wp[wt] = ssum;
        }
    }
    __syncthreads();
    if (tid < 8) {
        int blk = tid & 3, cc = tid >> 2;
        float* wp = (float*)(smem + SOFF_WP);
        float s = wp[blk * 4 + cc * 2 + 0] + wp[blk * 4 + cc * 2 + 1];
        out[(size_t)(i0 + blk) * NCAP + (c0 + cc)] = s / (float)cap_lens[c0 + cc];
    }
}

// ---------------------------------------------------------------------------
extern "C" void kernel_launch(void* const* d_in, const int* in_sizes, int n_in,
                              void* d_out, int out_size) {
    const float* imgs     = (const float*)d_in[0];
    const float* caps     = (const float*)d_in[1];
    const int*   cap_lens = (const int*)d_in[3];
    float*       out      = (float*)d_out;

    prep_kernel<<<512, 256>>>(imgs, caps, cap_lens);

    cudaFuncSetAttribute(main_kernel, cudaFuncAttributeMaxDynamicSharedMemorySize,
                         SMEM_TOTAL_MAIN);
    dim3 grid(NIMG / 4, NCAP / 2);
    main_kernel<<<grid, 384, SMEM_TOTAL_MAIN>>>(cap_lens, out);
}

// round 17
// speedup vs baseline: 1.1090x; 1.1090x over previous
#include <cuda_runtime.h>
#include <cuda_fp16.h>
#include <cstdint>
#include <math.h>

#define NIMG 256
#define NREG 36
#define NCAP 256
#define MAXW 60
#define CAPW 64
#define DIM  1024

#define SMOOTH 9.0f
#define EPSV   1e-8f
#define LEAK   0.1f

// ---------------------------------------------------------------------------
// Device global scratch
// ---------------------------------------------------------------------------
__device__ __half g_caps_h[NCAP * CAPW * DIM];
__device__ __half g_imgs_h[NIMG * NREG * DIM];
__device__ float g_G[NIMG * NREG * NREG];
__device__ float g_w1[NCAP * MAXW];

// ---------------------------------------------------------------------------
// Helpers
// ---------------------------------------------------------------------------
__device__ __forceinline__ uint32_t smem_to_u32(const void* p) {
    uint32_t a;
    asm("{ .reg .u64 t; cvta.to.shared.u64 t, %1; cvt.u32.u64 %0, t; }"
        : "=r"(a) : "l"(p));
    return a;
}
__device__ __forceinline__ void cp16(uint32_t dst, const void* src) {
    asm volatile("cp.async.cg.shared.global [%0], [%1], 16;" :: "r"(dst), "l"(src) : "memory");
}
__device__ __forceinline__ void ldsm_x4(uint32_t &r0, uint32_t &r1, uint32_t &r2,
                                        uint32_t &r3, uint32_t addr) {
    asm volatile("ldmatrix.sync.aligned.m8n8.x4.shared.b16 {%0,%1,%2,%3}, [%4];"
                 : "=r"(r0), "=r"(r1), "=r"(r2), "=r"(r3) : "r"(addr));
}
__device__ __forceinline__ void ldsm_x2(uint32_t &r0, uint32_t &r1, uint32_t addr) {
    asm volatile("ldmatrix.sync.aligned.m8n8.x2.shared.b16 {%0,%1}, [%2];"
                 : "=r"(r0), "=r"(r1) : "r"(addr));
}
__device__ __forceinline__ void mma_f16(float &c0, float &c1, float &c2, float &c3,
                                        uint32_t a0, uint32_t a1, uint32_t a2, uint32_t a3,
                                        uint32_t b0, uint32_t b1) {
    asm volatile("mma.sync.aligned.m16n8k16.row.col.f32.f16.f16.f32 "
                 "{%0,%1,%2,%3}, {%4,%5,%6,%7}, {%8,%9}, {%0,%1,%2,%3};"
                 : "+f"(c0), "+f"(c1), "+f"(c2), "+f"(c3)
                 : "r"(a0), "r"(a1), "r"(a2), "r"(a3), "r"(b0), "r"(b1));
}
__device__ __forceinline__ unsigned long long pack2(float lo, float hi) {
    unsigned long long r;
    asm("mov.b64 %0, {%1, %2};" : "=l"(r) : "f"(lo), "f"(hi));
    return r;
}
__device__ __forceinline__ void unpack2(unsigned long long v, float &lo, float &hi) {
    asm("mov.b64 {%0, %1}, %2;" : "=f"(lo), "=f"(hi) : "l"(v));
}
__device__ __forceinline__ void ffma2(unsigned long long &d,
                                      unsigned long long a,
                                      unsigned long long b) {
    asm("fma.rn.f32x2 %0, %1, %2, %0;" : "+l"(d) : "l"(a), "l"(b));
}
__device__ __forceinline__ float warpSum(float v) {
    v += __shfl_xor_sync(0xffffffffu, v, 16);
    v += __shfl_xor_sync(0xffffffffu, v, 8);
    v += __shfl_xor_sync(0xffffffffu, v, 4);
    v += __shfl_xor_sync(0xffffffffu, v, 2);
    v += __shfl_xor_sync(0xffffffffu, v, 1);
    return v;
}
__device__ __forceinline__ float dot4(float4 a, float4 b) {
    return a.x * b.x + a.y * b.y + a.z * b.z + a.w * b.w;
}

// ---------------------------------------------------------------------------
// Merged prep: blocks [0,256) caps; [256,512) imgs + Gram (4x4 reg-blocked)
// ---------------------------------------------------------------------------
__global__ void prep_kernel(const float* __restrict__ imgs,
                            const float* __restrict__ caps,
                            const int* __restrict__ cap_lens) {
    __shared__ float chunk[NREG * 132];
    if (blockIdx.x < 256) {
        const int c = blockIdx.x;
        const int wid = threadIdx.x >> 5, lane = threadIdx.x & 31;
        const int len = cap_lens[c];
        for (int w = wid; w < CAPW; w += 8) {
            size_t dsto = ((size_t)c * CAPW + w) * DIM;
            if (w < len) {
                const float* row = caps + ((size_t)c * MAXW + w) * DIM;
                float ss = 0.f;
#pragma unroll
                for (int j = 0; j < 8; j++) {
                    float4 v = *(const float4*)(row + j * 128 + lane * 4);
                    ss += v.x * v.x + v.y * v.y + v.z * v.z + v.w * v.w;
                    size_t o = dsto + j * 128 + lane * 4;
                    *(__half2*)(g_caps_h + o)     = __floats2half2_rn(v.x, v.y);
                    *(__half2*)(g_caps_h + o + 2) = __floats2half2_rn(v.z, v.w);
                }
                ss = warpSum(ss);
                if (lane == 0 && w < MAXW) g_w1[c * MAXW + w] = sqrtf(ss);
            } else {
                uint2 z = make_uint2(0u, 0u);
#pragma unroll
                for (int j = 0; j < 8; j++)
                    *(uint2*)(g_caps_h + dsto + j * 128 + lane * 4) = z;
                if (lane == 0 && w < MAXW) g_w1[c * MAXW + w] = 0.f;
            }
        }
    } else {
        const int i = blockIdx.x - 256;
        const int ty = threadIdx.x / 9;
        const int tx = threadIdx.x % 9;
        float acc[4][4];
#pragma unroll
        for (int u = 0; u < 4; u++)
#pragma unroll
            for (int v = 0; v < 4; v++) acc[u][v] = 0.f;

        for (int d0 = 0; d0 < DIM; d0 += 128) {
            __syncthreads();
            for (int idx = threadIdx.x; idx < NREG * 32; idx += 256) {
                int r = idx >> 5, dq = idx & 31;
                size_t e = ((size_t)i * NREG + r) * DIM + d0 + dq * 4;
                float4 v = *(const float4*)(imgs + e);
                *(float4*)(chunk + r * 132 + dq * 4) = v;
                *(__half2*)(g_imgs_h + e)     = __floats2half2_rn(v.x, v.y);
                *(__half2*)(g_imgs_h + e + 2) = __floats2half2_rn(v.z, v.w);
            }
            __syncthreads();
            if (threadIdx.x < 81) {
                const float4* A0 = (const float4*)(chunk + (ty * 4 + 0) * 132);
                const float4* A1 = (const float4*)(chunk + (ty * 4 + 1) * 132);
                const float4* A2 = (const float4*)(chunk + (ty * 4 + 2) * 132);
                const float4* A3 = (const float4*)(chunk + (ty * 4 + 3) * 132);
                const float4* B0 = (const float4*)(chunk + (tx * 4 + 0) * 132);
                const float4* B1 = (const float4*)(chunk + (tx * 4 + 1) * 132);
                const float4* B2 = (const float4*)(chunk + (tx * 4 + 2) * 132);
                const float4* B3 = (const float4*)(chunk + (tx * 4 + 3) * 132);
#pragma unroll 8
                for (int q = 0; q < 32; q++) {
                    float4 a0 = A0[q], a1 = A1[q], a2 = A2[q], a3 = A3[q];
                    float4 b0 = B0[q], b1 = B1[q], b2 = B2[q], b3 = B3[q];
                    acc[0][0] += dot4(a0, b0); acc[0][1] += dot4(a0, b1);
                    acc[0][2] += dot4(a0, b2); acc[0][3] += dot4(a0, b3);
                    acc[1][0] += dot4(a1, b0); acc[1][1] += dot4(a1, b1);
                    acc[1][2] += dot4(a1, b2); acc[1][3] += dot4(a1, b3);
                    acc[2][0] += dot4(a2, b0); acc[2][1] += dot4(a2, b1);
                    acc[2][2] += dot4(a2, b2); acc[2][3] += dot4(a2, b3);
                    acc[3][0] += dot4(a3, b0); acc[3][1] += dot4(a3, b1);
                    acc[3][2] += dot4(a3, b2); acc[3][3] += dot4(a3, b3);
                }
            }
        }
        if (threadIdx.x < 81) {
            float* Gi = g_G + (size_t)i * NREG * NREG;
#pragma unroll
            for (int u = 0; u < 4; u++) {
                float4 v0 = make_float4(acc[u][0], acc[u][1], acc[u][2], acc[u][3]);
                *(float4*)(Gi + (ty * 4 + u) * NREG + tx * 4) = v0;
            }
        }
    }
}

// ---------------------------------------------------------------------------
// Main fused kernel: fp16 GEMM M=128 x N=144 x K=1024 + SCAN epilogue.
// 256 threads / 8 warps (warp tile 32x72), 3-stage pipeline, 2 CTAs/SM.
// Gram/w1 staged AFTER the GEMM (stage buffers dead -> safe union).
// ---------------------------------------------------------------------------
#define STAGE_BYTES 34816
#define SB_OFF      16384
#define SOFF_SCALE  75776
#define SOFF_W1     76928
#define SOFF_WP     77440
#define SOFF_G      77504
#define SMEM_TOTAL_MAIN 104448
#define NCHUNK 16
#define SSTRIDE 148   // floats per S row

__device__ __forceinline__ void load_stage(uint32_t sbase, int chunk, int tid,
                                           int arowbase, int browbase) {
    const int k0 = chunk << 6;
    const uint32_t sA = sbase + (chunk % 3) * STAGE_BYTES;
    const uint32_t sB = sA + SB_OFF;
#pragma unroll
    for (int t = 0; t < 4; t++) {
        int o = tid + t * 256;
        int row = o >> 3, seg = o & 7;
        cp16(sA + row * 128 + (((seg ^ (row & 7))) << 4),
             g_caps_h + (((size_t)(arowbase + row)) << 10) + k0 + (seg << 3));
    }
#pragma unroll
    for (int t = 0; t < 4; t++) {
        int o = tid + t * 256;
        int row = o >> 3, seg = o & 7;
        cp16(sB + row * 128 + (((seg ^ (row & 7))) << 4),
             g_imgs_h + (((size_t)(browbase + row)) << 10) + k0 + (seg << 3));
    }
    {
        int o = tid + 1024;
        if (o < 1152) {
            int row = o >> 3, seg = o & 7;
            cp16(sB + row * 128 + (((seg ^ (row & 7))) << 4),
                 g_imgs_h + (((size_t)(browbase + row)) << 10) + k0 + (seg << 3));
        }
    }
    asm volatile("cp.async.commit_group;" ::: "memory");
}

__global__ void __launch_bounds__(256, 2)
main_kernel(const int* __restrict__ cap_lens, float* __restrict__ out) {
    extern __shared__ __align__(16) char smem[];
    const uint32_t sb = smem_to_u32(smem);
    const int tid = threadIdx.x, lane = tid & 31, wid = tid >> 5;
    const int c0 = blockIdx.y * 2;
    const int i0 = blockIdx.x * 4;
    const int arowbase = blockIdx.y * 128;
    const int browbase = blockIdx.x * 144;

    float acc[72];
#pragma unroll
    for (int j = 0; j < 72; j++) acc[j] = 0.f;

    load_stage(sb, 0, tid, arowbase, browbase);
    load_stage(sb, 1, tid, arowbase, browbase);

    const int mstrip = wid & 3;
    const int mbase = mstrip * 32;
    const int ncb = (wid >> 2) * 72;
    const bool gemm_active =
        ((mstrip & 1) == 0) || (cap_lens[c0 + (mstrip >> 1)] > 32);

    const int a_roff = lane & 15;
    const int a_seg0 = lane >> 4;
    const int b_roff = ((lane >> 4) << 3) + (lane & 7);
    const int b_seg0 = (lane >> 3) & 1;
    const int l16 = lane & 15;
    const int b2_roff = l16 & 7;
    const int b2_seg0 = (l16 >> 3) & 1;
    const int sw = lane & 7;

    for (int i = 0; i < NCHUNK; i++) {
        if (i == NCHUNK - 1) asm volatile("cp.async.wait_group 0;" ::: "memory");
        else                 asm volatile("cp.async.wait_group 1;" ::: "memory");
        __syncthreads();
        if (i + 2 < NCHUNK)
            load_stage(sb, i + 2, tid, arowbase, browbase);

        if (gemm_active) {
            const uint32_t As = sb + (i % 3) * STAGE_BYTES;
            const uint32_t Bs = As + SB_OFF;
#pragma unroll
            for (int ks = 0; ks < 4; ks++) {
                uint32_t a[2][4];
#pragma unroll
                for (int s2 = 0; s2 < 2; s2++) {
                    int row = mbase + s2 * 16 + a_roff;
                    int seg = (ks * 2 + a_seg0) ^ sw;
                    ldsm_x4(a[s2][0], a[s2][1], a[s2][2], a[s2][3],
                            As + row * 128 + (seg << 4));
                }
                uint32_t bh0, bh1;
                {
                    int row = ncb + 64 + b2_roff;
                    int seg = (ks * 2 + b2_seg0) ^ sw;
                    ldsm_x2(bh0, bh1, Bs + row * 128 + (seg << 4));
                }
#pragma unroll
                for (int t = 0; t < 4; t++) {
                    uint32_t b0, b1, b2, b3;
                    int row = ncb + t * 16 + b_roff;
                    int seg = (ks * 2 + b_seg0) ^ sw;
                    ldsm_x4(b0, b1, b2, b3, Bs + row * 128 + (seg << 4));
#pragma unroll
                    for (int s2 = 0; s2 < 2; s2++) {
                        int j0 = s2 * 36 + t * 8;
                        mma_f16(acc[j0 + 0], acc[j0 + 1], acc[j0 + 2], acc[j0 + 3],
                                a[s2][0], a[s2][1], a[s2][2], a[s2][3], b0, b1);
                        mma_f16(acc[j0 + 4], acc[j0 + 5], acc[j0 + 6], acc[j0 + 7],
                                a[s2][0], a[s2][1], a[s2][2], a[s2][3], b2, b3);
                    }
                }
#pragma unroll
                for (int s2 = 0; s2 < 2; s2++) {
                    int j0 = s2 * 36 + 32;
                    mma_f16(acc[j0 + 0], acc[j0 + 1], acc[j0 + 2], acc[j0 + 3],
                            a[s2][0], a[s2][1], a[s2][2], a[s2][3], bh0, bh1);
                }
            }
        }
    }
    __syncthreads();   // stages fully consumed before S/Gram overwrite them

    // ---------------- write S (skip dead strips) + stage Gram / w1 ---------
    float* S = (float*)smem;
    if (gemm_active) {
        const int cA = (lane & 3) * 2;
        const int rA = lane >> 2;
#pragma unroll
        for (int s2 = 0; s2 < 2; s2++) {
            int r1 = mbase + s2 * 16 + rA;
#pragma unroll
            for (int j = 0; j < 9; j++) {
                int col = ncb + j * 8 + cA;
                *(float2*)(S + r1 * SSTRIDE + col) =
                    make_float2(acc[s2 * 36 + j * 4 + 0], acc[s2 * 36 + j * 4 + 1]);
                *(float2*)(S + (r1 + 8) * SSTRIDE + col) =
                    make_float2(acc[s2 * 36 + j * 4 + 2], acc[s2 * 36 + j * 4 + 3]);
            }
        }
    }
    {
        float* Gs = (float*)(smem + SOFF_G);
        if (tid < 4 * NREG) {
            int blk = tid / NREG, r = tid - blk * NREG;
            const float4* src = (const float4*)(g_G + ((size_t)(i0 + blk) * NREG + r) * NREG);
            float4* dst = (float4*)(Gs + (blk * NREG + r) * 40);
#pragma unroll
            for (int q = 0; q < 9; q++) dst[q] = src[q];
            dst[9] = make_float4(0.f, 0.f, 0.f, 0.f);
        }
        float* w1s = (float*)(smem + SOFF_W1);
        if (tid >= 128) {
            int p = tid - 128;
            int cc = p >> 6, w = p & 63;
            w1s[p] = (w < MAXW) ? g_w1[(c0 + cc) * MAXW + w] : 0.f;
        }
    }
    __syncthreads();

    // ---------------- column norms -> scale (float4, len-bounded) ----------
    float* scaleF = (float*)(smem + SOFF_SCALE);
    if (tid < 72) {
        int cap = tid >= 36;
        int j4 = (tid - cap * 36) * 4;
        int lenc = cap_lens[c0 + cap];
        const float* p = S + (cap * 64) * SSTRIDE + j4;
        float4 ssum = make_float4(0.f, 0.f, 0.f, 0.f);
        for (int w = 0; w < lenc; w++) {
            float4 v = *(const float4*)(p + w * SSTRIDE);
            v.x = (v.x < 0.f) ? LEAK * v.x : v.x;
            v.y = (v.y < 0.f) ? LEAK * v.y : v.y;
            v.z = (v.z < 0.f) ? LEAK * v.z : v.z;
            v.w = (v.w < 0.f) ? LEAK * v.w : v.w;
            ssum.x += v.x * v.x; ssum.y += v.y * v.y;
            ssum.z += v.z * v.z; ssum.w += v.w * v.w;
        }
        float4 sc;
        sc.x = SMOOTH / (sqrtf(ssum.x) + EPSV);
        sc.y = SMOOTH / (sqrtf(ssum.y) + EPSV);
        sc.z = SMOOTH / (sqrtf(ssum.z) + EPSV);
        sc.w = SMOOTH / (sqrtf(ssum.w) + EPSV);
        *(float4*)(scaleF + cap * 144 + j4) = sc;
    }
    __syncthreads();

    // ---------------- per-row epilogue (256 threads, 2 blks each) ----------
    {
        const int row = tid & 127;
        const int pair = tid >> 7;
        const int cap = row >> 6;
        const int word = row & 63;
        const int mylen = cap_lens[c0 + cap];
        const int wstart = ((wid & 1) << 5);
        const bool warp_active = (wstart < mylen);
        const bool valid = word < mylen;
        float* wp = (float*)(smem + SOFF_WP);

        if (!warp_active) {
            if (lane == 0) { wp[wid * 2 + 0] = 0.f; wp[wid * 2 + 1] = 0.f; }
        } else {
            const float myw1 = ((const float*)(smem + SOFF_W1))[row];
            const float* Srow = S + row * SSTRIDE;
#pragma unroll
            for (int bq = 0; bq < 2; bq++) {
                const int blk = pair * 2 + bq;
                const float* scl = scaleF + cap * 144 + blk * 36;
                float raw[36], e[40];
                {
                    const float4* p4 = (const float4*)(Srow + blk * 36);
#pragma unroll
                    for (int q = 0; q < 9; q++) {
                        float4 v = p4[q];
                        raw[q * 4 + 0] = v.x; raw[q * 4 + 1] = v.y;
                        raw[q * 4 + 2] = v.z; raw[q * 4 + 3] = v.w;
                    }
                }
                float se = 0.f;
#pragma unroll
                for (int r = 0; r < 36; r++) {
                    float v = raw[r];
                    float l = ((v < 0.f) ? LEAK * v : v) * scl[r];
                    e[r] = __expf(l);
                    se += e[r];
                }
                e[36] = 0.f; e[37] = 0.f; e[38] = 0.f; e[39] = 0.f;
                float inv = 1.f / se;
                float w12 = 0.f;
#pragma unroll
                for (int r = 0; r < 36; r++) w12 += e[r] * raw[r];
                w12 *= inv;

                unsigned long long ep[20];
#pragma unroll
                for (int q = 0; q < 20; q++) ep[q] = pack2(e[2 * q], e[2 * q + 1]);
                const float* Gbase =
                    (const float*)(smem + SOFF_G) + (size_t)blk * NREG * 40;
                float t = 0.f;
#pragma unroll
                for (int r = 0; r < 36; r++) {
                    const float* grow = Gbase + r * 40;
                    const unsigned long long* grow2 = (const unsigned long long*)grow;
                    float head = 0.f;
                    int q0 = r + 1;
                    if (q0 & 1) { head = grow[q0] * e[q0]; q0++; }
                    unsigned long long d2 = 0ull;
#pragma unroll
                    for (int qq = q0 >> 1; qq < 20; qq++) ffma2(d2, grow2[qq], ep[qq]);
                    float dlo, dhi;
                    unpack2(d2, dlo, dhi);
                    t += e[r] * (grow[r] * e[r] + 2.f * (head + dlo + dhi));
                }
                float w2 = sqrtf(t) * inv;
                float sim = w12 / fmaxf(myw1 * w2, EPSV);
                sim = valid ? sim : 0.f;

                float ssum = warpSum(sim);
                if (lane == 0) wp[wid * 2 + bq] = ssum;
            }
        }
    }
    __syncthreads();
    if (tid < 8) {
        int blk = tid & 3, cc = tid >> 2;
        int p = blk >> 1, b = blk & 1;
        float* wp = (float*)(smem + SOFF_WP);
        int w0 = p * 4 + cc * 2;
        float s = wp[w0 * 2 + b] + wp[(w0 + 1) * 2 + b];
        out[(size_t)(i0 + blk) * NCAP + (c0 + cc)] = s / (float)cap_lens[c0 + cc];
    }
}

// ---------------------------------------------------------------------------
extern "C" void kernel_launch(void* const* d_in, const int* in_sizes, int n_in,
                              void* d_out, int out_size) {
    const float* imgs     = (const float*)d_in[0];
    const float* caps     = (const float*)d_in[1];
    const int*   cap_lens = (const int*)d_in[3];
    float*       out      = (float*)d_out;

    prep_kernel<<<512, 256>>>(imgs, caps, cap_lens);

    cudaFuncSetAttribute(main_kernel, cudaFuncAttributeMaxDynamicSharedMemorySize,
                         SMEM_TOTAL_MAIN);
    dim3 grid(NIMG / 4, NCAP / 2);
    main_kernel<<<grid, 256, SMEM_TOTAL_MAIN>>>(cap_lens, out);
}